// round 2
// baseline (speedup 1.0000x reference)
#include <cuda_runtime.h>
#include <stdint.h>
#include <math.h>

// Field_64682207478165: instant-NGP hash-grid encode (L=16, T=2^19, F=2) + MLP 35->32->32->1 (ELU)
// Inputs (metadata order): x (N,3) f32, table (16, 2^19, 2) f32, W0 (35,32), b0 (32),
//                          W1 (32,32), b1 (32), Wout (32,1), bout (1). Output: (N,1) f32.

#define NLVL 16
#define TSZ  (1u << 19)
#define HID  32
#define NFEAT 35   // 3 coords + 16*2 features

typedef unsigned int u32;

struct LevelScales { float s[NLVL]; };

__global__ __launch_bounds__(256, 2) void field_kernel(
    const float* __restrict__ x,
    const float* __restrict__ table,
    const float* __restrict__ W0,
    const float* __restrict__ b0,
    const float* __restrict__ W1,
    const float* __restrict__ b1,
    const float* __restrict__ Wout,
    const float* __restrict__ bout,
    float* __restrict__ out,
    int n, LevelScales sc)
{
    __shared__ float sW0[NFEAT * HID];
    __shared__ float sW1[HID * HID];
    __shared__ float sB0[HID], sB1[HID], sWo[HID];
    __shared__ float sBo;

    const int tid = threadIdx.x;
    for (int i = tid; i < NFEAT * HID; i += 256) sW0[i] = W0[i];
    for (int i = tid; i < HID * HID;   i += 256) sW1[i] = W1[i];
    if (tid < HID) { sB0[tid] = b0[tid]; sB1[tid] = b1[tid]; sWo[tid] = Wout[tid]; }
    if (tid == 0) sBo = bout[0];
    __syncthreads();

    const int i = blockIdx.x * 256 + tid;
    if (i >= n) return;

    // normalize coords exactly like reference: xn = (x + 1) / 2  (SCALE = 1)
    const float xn0 = (x[3*i + 0] + 1.0f) * 0.5f;
    const float xn1 = (x[3*i + 1] + 1.0f) * 0.5f;
    const float xn2 = (x[3*i + 2] + 1.0f) * 0.5f;

    float feat[NFEAT];
    feat[0] = xn0; feat[1] = xn1; feat[2] = xn2;

    const u32 P1 = 2654435761u, P2 = 805459861u;
    const u32 msk = TSZ - 1u;

    #pragma unroll
    for (int l = 0; l < NLVL; ++l) {
        const float s = sc.s[l];
        const float px = xn0 * s, py = xn1 * s, pz = xn2 * s;
        const float f0 = floorf(px), f1 = floorf(py), f2 = floorf(pz);
        const float wx = px - f0, wy = py - f1, wz = pz - f2;
        const u32 ix = (u32)f0, iy = (u32)f1, iz = (u32)f2;

        const u32 hx0 = ix,             hx1 = ix + 1u;
        const u32 hy0 = iy * P1,        hy1 = (iy + 1u) * P1;
        const u32 hz0 = iz * P2,        hz1 = (iz + 1u) * P2;

        const float2* __restrict__ tb = ((const float2*)table) + (size_t)l * TSZ;

        const float2 g000 = __ldg(tb + ((hx0 ^ hy0 ^ hz0) & msk));
        const float2 g100 = __ldg(tb + ((hx1 ^ hy0 ^ hz0) & msk));
        const float2 g010 = __ldg(tb + ((hx0 ^ hy1 ^ hz0) & msk));
        const float2 g110 = __ldg(tb + ((hx1 ^ hy1 ^ hz0) & msk));
        const float2 g001 = __ldg(tb + ((hx0 ^ hy0 ^ hz1) & msk));
        const float2 g101 = __ldg(tb + ((hx1 ^ hy0 ^ hz1) & msk));
        const float2 g011 = __ldg(tb + ((hx0 ^ hy1 ^ hz1) & msk));
        const float2 g111 = __ldg(tb + ((hx1 ^ hy1 ^ hz1) & msk));

        const float ux = 1.0f - wx, uy = 1.0f - wy, uz = 1.0f - wz;
        const float w000 = ux*uy*uz, w100 = wx*uy*uz, w010 = ux*wy*uz, w110 = wx*wy*uz;
        const float w001 = ux*uy*wz, w101 = wx*uy*wz, w011 = ux*wy*wz, w111 = wx*wy*wz;

        float a0 = w000 * g000.x; float a1 = w000 * g000.y;
        a0 = fmaf(w100, g100.x, a0); a1 = fmaf(w100, g100.y, a1);
        a0 = fmaf(w010, g010.x, a0); a1 = fmaf(w010, g010.y, a1);
        a0 = fmaf(w110, g110.x, a0); a1 = fmaf(w110, g110.y, a1);
        a0 = fmaf(w001, g001.x, a0); a1 = fmaf(w001, g001.y, a1);
        a0 = fmaf(w101, g101.x, a0); a1 = fmaf(w101, g101.y, a1);
        a0 = fmaf(w011, g011.x, a0); a1 = fmaf(w011, g011.y, a1);
        a0 = fmaf(w111, g111.x, a0); a1 = fmaf(w111, g111.y, a1);

        feat[3 + 2*l]     = a0;
        feat[3 + 2*l + 1] = a1;
    }

    // ---- MLP: h1 = elu(feat @ W0 + b0) ----
    float h1[HID];
    #pragma unroll
    for (int j = 0; j < HID; ++j) h1[j] = sB0[j];
    #pragma unroll
    for (int k = 0; k < NFEAT; ++k) {
        const float f = feat[k];
        #pragma unroll
        for (int j = 0; j < HID; ++j)
            h1[j] = fmaf(f, sW0[k * HID + j], h1[j]);
    }
    #pragma unroll
    for (int j = 0; j < HID; ++j)
        h1[j] = (h1[j] > 0.0f) ? h1[j] : (__expf(h1[j]) - 1.0f);

    // ---- h2 = elu(h1 @ W1 + b1) ----
    float h2[HID];
    #pragma unroll
    for (int j = 0; j < HID; ++j) h2[j] = sB1[j];
    #pragma unroll
    for (int k = 0; k < HID; ++k) {
        const float f = h1[k];
        #pragma unroll
        for (int j = 0; j < HID; ++j)
            h2[j] = fmaf(f, sW1[k * HID + j], h2[j]);
    }
    #pragma unroll
    for (int j = 0; j < HID; ++j)
        h2[j] = (h2[j] > 0.0f) ? h2[j] : (__expf(h2[j]) - 1.0f);

    // ---- out = h2 @ Wout + bout ----
    float acc = sBo;
    #pragma unroll
    for (int j = 0; j < HID; ++j) acc = fmaf(h2[j], sWo[j], acc);

    out[i] = acc;
}

extern "C" void kernel_launch(void* const* d_in, const int* in_sizes, int n_in,
                              void* d_out, int out_size)
{
    const float* x     = (const float*)d_in[0];
    const float* table = (const float*)d_in[1];
    const float* W0    = (const float*)d_in[2];
    const float* b0    = (const float*)d_in[3];
    const float* W1    = (const float*)d_in[4];
    const float* b1    = (const float*)d_in[5];
    const float* Wout  = (const float*)d_in[6];
    const float* bout  = (const float*)d_in[7];
    float* out = (float*)d_out;

    const int n = in_sizes[0] / 3;

    // per-level grid scales, computed in double to bit-match the reference's
    // f64 python scalar -> f32 weak-type promotion: s_l = f32(16 * B^l - 1)
    LevelScales sc;
    const double B = exp(log(512.0 / 16.0) / 15.0);   // = 2^(1/3)
    for (int l = 0; l < NLVL; ++l)
        sc.s[l] = (float)(16.0 * pow(B, (double)l) - 1.0);

    const int blocks = (n + 255) / 256;
    field_kernel<<<blocks, 256>>>(x, table, W0, b0, W1, b1, Wout, bout, out, n, sc);
}